// round 1
// baseline (speedup 1.0000x reference)
#include <cuda_runtime.h>

#define NTHREADS 256
#define TB 8              // tokens per batch
#define EDIM 1024
#define NQ 8
#define PSTRIDE 257       // psum row stride in floats (odd -> conflict-free)
#define NGROUPS (TB*NQ)   // 64 (token,qubit) groups per batch
#define SMEM_FLOATS (NGROUPS*PSTRIDE + 64 + 8 + 8)

__global__ __launch_bounds__(NTHREADS, 2)
void qff_kernel(const float* __restrict__ x,
                const float* __restrict__ W_in,
                const float* __restrict__ b_in,
                const float* __restrict__ theta,
                const float* __restrict__ W_out,
                const float* __restrict__ b_out,
                float* __restrict__ out,
                int n_tokens)
{
    extern __shared__ float sm[];
    float* psum = sm;                       // NGROUPS * PSTRIDE
    float* zsm  = sm + NGROUPS*PSTRIDE;     // 64 floats (16B aligned: 65792 % 16 == 0)
    float* cth  = zsm + 64;                 // 8: cos(theta)
    float* bi   = cth + 8;                  // 8: b_in

    const int tid  = threadIdx.x;
    const int lane = tid & 31;
    const int wrp  = tid >> 5;

    if (tid < NQ) { cth[tid] = cosf(theta[tid]); bi[tid] = b_in[tid]; }

    // ---- register-resident weights (loaded once per persistent block) ----
    float win[NQ][4];
#pragma unroll
    for (int q = 0; q < NQ; q++) {
        float4 w = reinterpret_cast<const float4*>(W_in + q*EDIM)[tid];
        win[q][0]=w.x; win[q][1]=w.y; win[q][2]=w.z; win[q][3]=w.w;
    }
    float4 wA[4], wB[4];                    // W_out rows for e = 4*tid .. 4*tid+3
#pragma unroll
    for (int j = 0; j < 4; j++) {
        wA[j] = reinterpret_cast<const float4*>(W_out)[(4*tid+j)*2 + 0];
        wB[j] = reinterpret_cast<const float4*>(W_out)[(4*tid+j)*2 + 1];
    }
    float4 bo = reinterpret_cast<const float4*>(b_out)[tid];
    float boa[4] = {bo.x, bo.y, bo.z, bo.w};

    __syncthreads();

    const int q2 = lane >> 2;   // qubit handled by this lane in stage 2
    const int c2 = lane & 3;    // chunk within the 256 partials
    const int nbatches = n_tokens / TB;

    for (int batch = blockIdx.x; batch < nbatches; batch += gridDim.x) {
        const long tok0 = (long)batch * TB;
        const float4* xrow = reinterpret_cast<const float4*>(x) + tok0*(EDIM/4) + tid;

        // ---- phase 1: partial angle sums ----
        float4 xv[TB];
#pragma unroll
        for (int t = 0; t < TB; t++) xv[t] = xrow[t*(EDIM/4)];

#pragma unroll
        for (int t = 0; t < TB; t++) {
#pragma unroll
            for (int q = 0; q < NQ; q++) {
                float a = xv[t].x * win[q][0];
                a = fmaf(xv[t].y, win[q][1], a);
                a = fmaf(xv[t].z, win[q][2], a);
                a = fmaf(xv[t].w, win[q][3], a);
                psum[(t*NQ + q)*PSTRIDE + tid] = a;   // bank (t*8+q+tid)%32: conflict-free
            }
        }
        __syncthreads();

        // ---- stage 2: warp `wrp` reduces token tok0+wrp; z prefix products ----
        {
            const float* row = psum + (wrp*NQ + q2)*PSTRIDE + c2*64;
            float s0=0.f, s1=0.f, s2=0.f, s3=0.f;
#pragma unroll
            for (int j0 = 0; j0 < 64; j0 += 4) {
                int j = (j0 + 8*c2) & 63;             // bank stagger: (q2+8*c2+j0)%32 distinct
                s0 += row[j+0];
                s1 += row[j+1];
                s2 += row[j+2];
                s3 += row[j+3];
            }
            float s = (s0+s1) + (s2+s3);
            s += __shfl_down_sync(0xffffffffu, s, 1);
            s += __shfl_down_sync(0xffffffffu, s, 2);  // c2==0 lane holds full dot
            float m = cth[q2] * cosf(s + bi[q2]);      // m_q = cos(theta_q)*cos(ang_q)
            float zv = m;                               // inclusive prefix product over q
#pragma unroll
            for (int off = 4; off <= 16; off <<= 1) {
                float p = __shfl_up_sync(0xffffffffu, zv, off);
                if (lane >= off) zv *= p;               // sources always c2==0 lanes
            }
            if (c2 == 0) zsm[wrp*NQ + q2] = zv;
        }
        __syncthreads();

        // ---- phase 3: out = relu(z @ W_out^T + b_out) ----
        float4* orow = reinterpret_cast<float4*>(out) + tok0*(EDIM/4) + tid;
#pragma unroll
        for (int t = 0; t < TB; t++) {
            float4 zlo = reinterpret_cast<float4*>(zsm)[2*t+0];  // broadcast LDS.128
            float4 zhi = reinterpret_cast<float4*>(zsm)[2*t+1];
            float acc[4];
#pragma unroll
            for (int j = 0; j < 4; j++) {
                float a = boa[j];
                a = fmaf(zlo.x, wA[j].x, a);
                a = fmaf(zlo.y, wA[j].y, a);
                a = fmaf(zlo.z, wA[j].z, a);
                a = fmaf(zlo.w, wA[j].w, a);
                a = fmaf(zhi.x, wB[j].x, a);
                a = fmaf(zhi.y, wB[j].y, a);
                a = fmaf(zhi.z, wB[j].z, a);
                a = fmaf(zhi.w, wB[j].w, a);
                acc[j] = fmaxf(a, 0.0f);
            }
            orow[t*(EDIM/4)] = make_float4(acc[0], acc[1], acc[2], acc[3]);
        }
        // no extra sync needed: next-iteration psum writes are fenced by the
        // post-stage2 sync; next zsm writes are fenced by the next post-phase1 sync.
    }
}

extern "C" void kernel_launch(void* const* d_in, const int* in_sizes, int n_in,
                              void* d_out, int out_size) {
    const float* x     = (const float*)d_in[0];
    const float* W_in  = (const float*)d_in[1];
    const float* b_in  = (const float*)d_in[2];
    const float* theta = (const float*)d_in[3];
    const float* W_out = (const float*)d_in[4];
    const float* b_out = (const float*)d_in[5];
    float* out = (float*)d_out;

    const int n_tokens = in_sizes[0] / EDIM;   // 32768

    const size_t smem = SMEM_FLOATS * sizeof(float);   // ~66 KB
    cudaFuncSetAttribute(qff_kernel, cudaFuncAttributeMaxDynamicSharedMemorySize, (int)smem);
    qff_kernel<<<296, NTHREADS, smem>>>(x, W_in, b_in, theta, W_out, b_out, out, n_tokens);
}